// round 2
// baseline (speedup 1.0000x reference)
#include <cuda_runtime.h>
#include <cuda_bf16.h>

#define BATCH   4
#define S_LEN   2048
#define EMB     1024
#define NHEADS  16
#define HDIM    64

// ---------------- scratch (static device globals; no allocation) -------------
__device__ float g_Q[(size_t)BATCH * S_LEN * EMB];                    // 33.5 MB
__device__ float g_K[(size_t)BATCH * S_LEN * EMB];
__device__ float g_V[(size_t)BATCH * S_LEN * EMB];
__device__ float g_O[(size_t)BATCH * S_LEN * EMB];
__device__ float g_P[(size_t)BATCH * NHEADS * S_LEN * S_LEN];         // 1 GiB

// ---------------- generic tiled SGEMM ---------------------------------------
// C[m,n] = alpha * sum_k A[m,k]*B'[k,n] (+ bias[n])
//   BT=true : B is [N,K] k-major (row n stride ldb)  -> C = A @ B^T
//   BT=false: B is [K,N] n-major (row k stride ldb)  -> C = A @ B
// grid.z batches: z -> (zb = z>>4, zh = z&15); per-operand offsets applied.
template<int BM, int BN, int BK, int TM, int TN, bool BT>
__global__ void __launch_bounds__(256)
gemm_kernel(const float* __restrict__ A, int lda,
            const float* __restrict__ B, int ldb,
            float* __restrict__ C, int ldc,
            int M, int N, int K, float alpha,
            const float* __restrict__ bias,
            long long aOffB, long long aOffH,
            long long bOffB, long long bOffH,
            long long cOffB, long long cOffH)
{
    constexpr int THREADS = (BM / TM) * (BN / TN);
    static_assert(THREADS == 256, "bad tile config");

    const int zb = blockIdx.z >> 4;
    const int zh = blockIdx.z & 15;
    A += zb * aOffB + zh * aOffH;
    B += zb * bOffB + zh * bOffH;
    C += zb * cOffB + zh * cOffH;

    __shared__ float As[BK][BM + 4];
    __shared__ float Bs[BK][BN + 4];

    const int tid = threadIdx.x;
    const int tx  = tid % (BN / TN);
    const int ty  = tid / (BN / TN);
    const int m0  = blockIdx.y * BM;
    const int n0  = blockIdx.x * BN;

    float acc[TM][TN] = {};

    constexpr int A_ITERS = (BM * BK / 4) / THREADS;
    constexpr int B_ITERS = (BN * BK / 4) / THREADS;

    for (int k0 = 0; k0 < K; k0 += BK) {
        // load A tile (BM x BK), k-contiguous rows, store transposed
        #pragma unroll
        for (int it = 0; it < A_ITERS; it++) {
            int i  = tid + it * THREADS;
            int r  = i / (BK / 4);
            int c4 = i % (BK / 4);
            float4 v = *(const float4*)(A + (long long)(m0 + r) * lda + k0 + c4 * 4);
            As[c4 * 4 + 0][r] = v.x;
            As[c4 * 4 + 1][r] = v.y;
            As[c4 * 4 + 2][r] = v.z;
            As[c4 * 4 + 3][r] = v.w;
        }
        if (BT) {
            #pragma unroll
            for (int it = 0; it < B_ITERS; it++) {
                int i  = tid + it * THREADS;
                int r  = i / (BK / 4);
                int c4 = i % (BK / 4);
                float4 v = *(const float4*)(B + (long long)(n0 + r) * ldb + k0 + c4 * 4);
                Bs[c4 * 4 + 0][r] = v.x;
                Bs[c4 * 4 + 1][r] = v.y;
                Bs[c4 * 4 + 2][r] = v.z;
                Bs[c4 * 4 + 3][r] = v.w;
            }
        } else {
            #pragma unroll
            for (int it = 0; it < B_ITERS; it++) {
                int i  = tid + it * THREADS;
                int r  = i / (BN / 4);
                int c4 = i % (BN / 4);
                float4 v = *(const float4*)(B + (long long)(k0 + r) * ldb + n0 + c4 * 4);
                *(float4*)&Bs[r][c4 * 4] = v;
            }
        }
        __syncthreads();

        #pragma unroll
        for (int kk = 0; kk < BK; kk++) {
            float a[TM], b[TN];
            #pragma unroll
            for (int i = 0; i < TM; i++) a[i] = As[kk][ty * TM + i];
            #pragma unroll
            for (int j = 0; j < TN; j++) b[j] = Bs[kk][tx * TN + j];
            #pragma unroll
            for (int i = 0; i < TM; i++)
                #pragma unroll
                for (int j = 0; j < TN; j++)
                    acc[i][j] += a[i] * b[j];
        }
        __syncthreads();
    }

    #pragma unroll
    for (int i = 0; i < TM; i++) {
        int m = m0 + ty * TM + i;
        #pragma unroll
        for (int j = 0; j < TN; j += 4) {
            int n = n0 + tx * TN + j;
            float4 v;
            v.x = acc[i][j + 0] * alpha + (bias ? bias[n + 0] : 0.f);
            v.y = acc[i][j + 1] * alpha + (bias ? bias[n + 1] : 0.f);
            v.z = acc[i][j + 2] * alpha + (bias ? bias[n + 2] : 0.f);
            v.w = acc[i][j + 3] * alpha + (bias ? bias[n + 3] : 0.f);
            *(float4*)(C + (long long)m * ldc + n) = v;
        }
    }
}

// ---------------- row softmax over g_P (2048 cols, 1 CTA = 1 row) -----------
__global__ void __launch_bounds__(256) softmax_kernel(float* __restrict__ P)
{
    const long long row = blockIdx.x;
    float4* p = reinterpret_cast<float4*>(P + row * (long long)S_LEN);
    const int tid  = threadIdx.x;
    const int lane = tid & 31;
    const int wid  = tid >> 5;

    float4 v0 = p[tid];
    float4 v1 = p[tid + 256];

    float m = fmaxf(fmaxf(fmaxf(v0.x, v0.y), fmaxf(v0.z, v0.w)),
                    fmaxf(fmaxf(v1.x, v1.y), fmaxf(v1.z, v1.w)));
    #pragma unroll
    for (int o = 16; o > 0; o >>= 1) m = fmaxf(m, __shfl_xor_sync(0xffffffffu, m, o));

    __shared__ float redm[8];
    __shared__ float reds[8];
    if (lane == 0) redm[wid] = m;
    __syncthreads();
    if (tid < 32) {
        float t = (lane < 8) ? redm[lane] : -1e30f;
        #pragma unroll
        for (int o = 4; o > 0; o >>= 1) t = fmaxf(t, __shfl_xor_sync(0xffffffffu, t, o));
        if (lane == 0) redm[0] = t;
    }
    __syncthreads();
    m = redm[0];

    v0.x = __expf(v0.x - m); v0.y = __expf(v0.y - m);
    v0.z = __expf(v0.z - m); v0.w = __expf(v0.w - m);
    v1.x = __expf(v1.x - m); v1.y = __expf(v1.y - m);
    v1.z = __expf(v1.z - m); v1.w = __expf(v1.w - m);

    float s = v0.x + v0.y + v0.z + v0.w + v1.x + v1.y + v1.z + v1.w;
    #pragma unroll
    for (int o = 16; o > 0; o >>= 1) s += __shfl_xor_sync(0xffffffffu, s, o);
    if (lane == 0) reds[wid] = s;
    __syncthreads();
    if (tid < 32) {
        float t = (lane < 8) ? reds[lane] : 0.f;
        #pragma unroll
        for (int o = 4; o > 0; o >>= 1) t += __shfl_xor_sync(0xffffffffu, t, o);
        if (lane == 0) reds[0] = t;
    }
    __syncthreads();
    const float inv = 1.f / reds[0];

    v0.x *= inv; v0.y *= inv; v0.z *= inv; v0.w *= inv;
    v1.x *= inv; v1.y *= inv; v1.z *= inv; v1.w *= inv;
    p[tid]       = v0;
    p[tid + 256] = v1;
}

// ---------------- mean over heads: P[B,H,S,S] -> out_mean[B,S,S] ------------
__global__ void __launch_bounds__(256) mean_kernel(const float* __restrict__ P,
                                                   float* __restrict__ outm)
{
    const long long idx = (long long)blockIdx.x * 256 + threadIdx.x;   // float4 idx
    const int b        = (int)(idx >> 20);        // 1048576 float4 per (b) slab
    const long long rem = idx & 1048575LL;
    const float4* src = reinterpret_cast<const float4*>(P) + ((long long)b << 24) + rem;

    float4 s = make_float4(0.f, 0.f, 0.f, 0.f);
    #pragma unroll
    for (int h = 0; h < NHEADS; h++) {
        float4 t = src[(long long)h << 20];
        s.x += t.x; s.y += t.y; s.z += t.z; s.w += t.w;
    }
    const float inv = 1.f / NHEADS;
    s.x *= inv; s.y *= inv; s.z *= inv; s.w *= inv;
    reinterpret_cast<float4*>(outm)[idx] = s;
}

// ---------------- launch -----------------------------------------------------
extern "C" void kernel_launch(void* const* d_in, const int* in_sizes, int n_in,
                              void* d_out, int out_size)
{
    const float* q  = (const float*)d_in[0];
    const float* k  = (const float*)d_in[1];
    const float* v  = (const float*)d_in[2];
    const float* Wq = (const float*)d_in[3];
    const float* bq = (const float*)d_in[4];
    const float* Wk = (const float*)d_in[5];
    const float* bk = (const float*)d_in[6];
    const float* Wv = (const float*)d_in[7];
    const float* bv = (const float*)d_in[8];
    const float* Wo = (const float*)d_in[9];
    const float* bo = (const float*)d_in[10];
    float* out = (float*)d_out;

    float *Qp, *Kp, *Vp, *Op, *Pp;
    cudaGetSymbolAddress((void**)&Qp, g_Q);
    cudaGetSymbolAddress((void**)&Kp, g_K);
    cudaGetSymbolAddress((void**)&Vp, g_V);
    cudaGetSymbolAddress((void**)&Op, g_O);
    cudaGetSymbolAddress((void**)&Pp, g_P);

    const long long SE  = (long long)S_LEN * EMB;        // 2097152
    const long long SS  = (long long)S_LEN * S_LEN;      // 4194304
    const int M = BATCH * S_LEN;                         // 8192

    // 1-3) projections: X @ W^T + b
    dim3 gproj(EMB / 128, M / 128, 1);
    gemm_kernel<128,128,16,8,8,true><<<gproj, 256>>>(q, EMB, Wq, EMB, Qp, EMB,
        M, EMB, EMB, 1.f, bq, 0,0,0,0,0,0);
    gemm_kernel<128,128,16,8,8,true><<<gproj, 256>>>(k, EMB, Wk, EMB, Kp, EMB,
        M, EMB, EMB, 1.f, bk, 0,0,0,0,0,0);
    gemm_kernel<128,128,16,8,8,true><<<gproj, 256>>>(v, EMB, Wv, EMB, Vp, EMB,
        M, EMB, EMB, 1.f, bv, 0,0,0,0,0,0);

    // 4) scores: P[b,h] = (Q_h @ K_h^T) / sqrt(D)
    dim3 gsc(S_LEN / 128, S_LEN / 128, BATCH * NHEADS);
    gemm_kernel<128,128,16,8,8,true><<<gsc, 256>>>(Qp, EMB, Kp, EMB, Pp, S_LEN,
        S_LEN, S_LEN, HDIM, 0.125f, nullptr,
        SE, HDIM,            // A offsets (b, h)
        SE, HDIM,            // B offsets
        (long long)NHEADS * SS, SS);  // C offsets

    // 5) softmax rows in-place
    softmax_kernel<<<BATCH * NHEADS * S_LEN, 256>>>(Pp);

    // 6) attn mean over heads -> second output region
    mean_kernel<<<(BATCH * S_LEN * S_LEN / 4) / 256, 256>>>(Pp, out + (long long)M * EMB);

    // 7) PV: O[b,:,h*64+d] = P[b,h] @ V_h
    dim3 gpv(1, S_LEN / 128, BATCH * NHEADS);
    gemm_kernel<128,64,16,8,4,false><<<gpv, 256>>>(Pp, S_LEN, Vp, EMB, Op, EMB,
        S_LEN, HDIM, S_LEN, 1.f, nullptr,
        (long long)NHEADS * SS, SS,
        SE, HDIM,
        SE, HDIM);

    // 8) output projection -> first output region
    gemm_kernel<128,128,16,8,8,true><<<gproj, 256>>>(Op, EMB, Wo, EMB, out, EMB,
        M, EMB, EMB, 1.f, bo, 0,0,0,0,0,0);
}